// round 1
// baseline (speedup 1.0000x reference)
#include <cuda_runtime.h>
#include <math.h>

// Problem constants
#define Bq   256   // batch
#define Tq   256   // sequence length
#define Cq   384   // embedding dim
#define Hq   64    // head dim
#define BT   (Bq * Tq)   // 65536 rows

// Scratch for q, k, v projections ([B, T, H] fp32 each)
__device__ float g_q[(size_t)BT * Hq];
__device__ float g_k[(size_t)BT * Hq];
__device__ float g_v[(size_t)BT * Hq];

// ----------------------------------------------------------------------------
// Kernel 1: QKV projection.  SGEMM  [BT x C] @ [C x H] -> [BT x H]
// 64x64 output tile per block (N=H=64 exactly), BK=32, 256 threads, 4x4 micro.
// grid = (BT/64, 3);  grid.y selects {Wq->g_q, Wk->g_k, Wv->g_v}
// ----------------------------------------------------------------------------
__global__ __launch_bounds__(256) void proj_kernel(
    const float* __restrict__ x,
    const float* __restrict__ Wq,
    const float* __restrict__ Wk,
    const float* __restrict__ Wv)
{
    const int which = blockIdx.y;
    const float* __restrict__ W  = (which == 0) ? Wq : (which == 1) ? Wk : Wv;
    float* __restrict__ out      = (which == 0) ? g_q : (which == 1) ? g_k : g_v;

    const int m0  = blockIdx.x * 64;
    const int tid = threadIdx.x;
    const int tx  = tid & 15;   // 0..15 -> output col group (4 cols)
    const int ty  = tid >> 4;   // 0..15 -> output row group (4 rows)

    __shared__ __align__(16) float As[32][64];  // [k][m]  (A transposed)
    __shared__ __align__(16) float Bs[32][64];  // [k][n]

    float acc[4][4] = {};

    for (int k0 = 0; k0 < Cq; k0 += 32) {
        // Load A tile (64 rows x 32 k), store transposed As[k][m]
        #pragma unroll
        for (int i = 0; i < 2; i++) {
            int lid = tid * 2 + i;            // 0..511 float4 slots
            int m   = lid >> 3;               // 0..63
            int kq  = lid & 7;                // 0..7  (k = kq*4)
            float4 v = *(const float4*)&x[(size_t)(m0 + m) * Cq + k0 + kq * 4];
            As[kq * 4 + 0][m] = v.x;
            As[kq * 4 + 1][m] = v.y;
            As[kq * 4 + 2][m] = v.z;
            As[kq * 4 + 3][m] = v.w;
        }
        // Load B tile (32 k x 64 n)
        #pragma unroll
        for (int i = 0; i < 2; i++) {
            int lid = tid * 2 + i;            // 0..511
            int k   = lid >> 4;               // 0..31
            int nq  = lid & 15;               // 0..15 (n = nq*4)
            *(float4*)&Bs[k][nq * 4] =
                *(const float4*)&W[(size_t)(k0 + k) * Hq + nq * 4];
        }
        __syncthreads();

        #pragma unroll
        for (int kk = 0; kk < 32; kk++) {
            float4 a4 = *(const float4*)&As[kk][ty * 4];
            float4 b4 = *(const float4*)&Bs[kk][tx * 4];
            float av[4] = {a4.x, a4.y, a4.z, a4.w};
            float bv[4] = {b4.x, b4.y, b4.z, b4.w};
            #pragma unroll
            for (int r = 0; r < 4; r++)
                #pragma unroll
                for (int c = 0; c < 4; c++)
                    acc[r][c] += av[r] * bv[c];
        }
        __syncthreads();
    }

    #pragma unroll
    for (int r = 0; r < 4; r++) {
        float4 v = make_float4(acc[r][0], acc[r][1], acc[r][2], acc[r][3]);
        *(float4*)&out[(size_t)(m0 + ty * 4 + r) * Hq + tx * 4] = v;
    }
}

// ----------------------------------------------------------------------------
// Kernel 2: causal attention per batch.
// One block per batch; K,V (256x64 fp32 each) staged in 128KB dynamic smem.
// One thread per query row; q-row and output accumulator in registers.
// Online softmax, rescale only on new max.
// ----------------------------------------------------------------------------
__global__ __launch_bounds__(256) void attn_kernel(float* __restrict__ outp)
{
    extern __shared__ __align__(16) float smem[];
    float* Ks = smem;              // [T][H]
    float* Vs = smem + Tq * Hq;    // [T][H]

    const int b   = blockIdx.x;
    const int row = threadIdx.x;   // query row (0..255)

    const float* __restrict__ kb = g_k + (size_t)b * Tq * Hq;
    const float* __restrict__ vb = g_v + (size_t)b * Tq * Hq;

    // Cooperative, coalesced load of K and V into smem
    for (int i = row; i < (Tq * Hq) / 4; i += blockDim.x) {
        ((float4*)Ks)[i] = ((const float4*)kb)[i];
        ((float4*)Vs)[i] = ((const float4*)vb)[i];
    }
    __syncthreads();

    // Load this thread's q row into registers
    float4 q[16];
    const float* qrow = g_q + ((size_t)b * Tq + row) * Hq;
    #pragma unroll
    for (int i = 0; i < 16; i++) q[i] = ((const float4*)qrow)[i];

    float4 o[16];
    #pragma unroll
    for (int i = 0; i < 16; i++) o[i] = make_float4(0.f, 0.f, 0.f, 0.f);

    const float scale = 1.0f / sqrtf((float)Cq);  // C^-0.5 (reference scaling)
    float m = -INFINITY;
    float l = 0.0f;

    for (int j = 0; j <= row; j++) {
        const float4* krow = (const float4*)(Ks + j * Hq);
        float s0 = 0.f, s1 = 0.f, s2 = 0.f, s3 = 0.f;
        #pragma unroll
        for (int i = 0; i < 16; i++) {
            float4 k4 = krow[i];
            s0 += q[i].x * k4.x;
            s1 += q[i].y * k4.y;
            s2 += q[i].z * k4.z;
            s3 += q[i].w * k4.w;
        }
        float s = ((s0 + s1) + (s2 + s3)) * scale;

        float p;
        if (s > m) {
            float corr = __expf(m - s);   // first iter: exp(-inf) = 0
            m = s;
            l *= corr;
            #pragma unroll
            for (int i = 0; i < 16; i++) {
                o[i].x *= corr; o[i].y *= corr;
                o[i].z *= corr; o[i].w *= corr;
            }
            p = 1.0f;
        } else {
            p = __expf(s - m);
        }
        l += p;

        const float4* vrow = (const float4*)(Vs + j * Hq);
        #pragma unroll
        for (int i = 0; i < 16; i++) {
            float4 v4 = vrow[i];
            o[i].x += p * v4.x;
            o[i].y += p * v4.y;
            o[i].z += p * v4.z;
            o[i].w += p * v4.w;
        }
    }

    const float inv = 1.0f / l;
    float* orow = outp + ((size_t)b * Tq + row) * Hq;
    #pragma unroll
    for (int i = 0; i < 16; i++) {
        float4 v = o[i];
        v.x *= inv; v.y *= inv; v.z *= inv; v.w *= inv;
        ((float4*)orow)[i] = v;
    }
}

// ----------------------------------------------------------------------------
extern "C" void kernel_launch(void* const* d_in, const int* in_sizes, int n_in,
                              void* d_out, int out_size)
{
    const float* x  = (const float*)d_in[0];
    const float* Wq = (const float*)d_in[1];
    const float* Wk = (const float*)d_in[2];
    const float* Wv = (const float*)d_in[3];
    float* out = (float*)d_out;

    (void)in_sizes; (void)n_in; (void)out_size;

    dim3 g1(BT / 64, 3);
    proj_kernel<<<g1, 256>>>(x, Wq, Wk, Wv);

    const int smem_bytes = 2 * Tq * Hq * (int)sizeof(float);  // 128 KB
    cudaFuncSetAttribute(attn_kernel,
                         cudaFuncAttributeMaxDynamicSharedMemorySize,
                         smem_bytes);
    attn_kernel<<<Bq, Tq, smem_bytes>>>(out);
}